// round 9
// baseline (speedup 1.0000x reference)
#include <cuda_runtime.h>
#include <math.h>

#define B_DIM 64
#define C_DIM 64
#define K_CL 8
#define HW 12544            // floats per plane
#define QF 3136             // floats per quarter-plane
#define QF4 784             // float4 per quarter
#define BC (B_DIM * C_DIM)  // 4096 planes
#define EPS 1e-6f
#define NTHR 256

// ---- device scratch -------------------------------------------------------
__device__ int   g_cid[B_DIM];
__device__ float g_lmda[B_DIM];
__device__ int   g_count[K_CL];
__device__ int   g_pbase[K_CL];      // plane-order base of cluster
__device__ int   g_plane_order[BC];  // planes sorted cluster-major
__device__ float g_q1[BC * 4];       // per-quarter partial sums
__device__ float g_q2[BC * 4];
__device__ float g_scale[BC];
__device__ float g_bias[BC];
__device__ int   g_curA[K_CL];       // reduce task cursors
__device__ int   g_curC[K_CL];       // apply task cursors
__device__ int   g_doneA[K_CL];      // completed reduce tasks
__device__ volatile int g_flag[K_CL];

// ---------------------------------------------------------------------------
// Kernel A: schedule (parallel, 1 block).
// ---------------------------------------------------------------------------
__global__ __launch_bounds__(256) void k_schedule(const float* __restrict__ cluster_map,
                                                  const float* __restrict__ lmda) {
    __shared__ int sh_cid[B_DIM];
    __shared__ int sh_sorted_b[B_DIM];
    __shared__ int sh_off[K_CL];
    __shared__ int sh_cnt[K_CL];

    const int tid = threadIdx.x;

    if (tid < B_DIM) {
        const float* row = cluster_map + tid * K_CL;
        float best = row[0];
        int bi = 0;
#pragma unroll
        for (int k = 1; k < K_CL; ++k) {
            float v = row[k];
            if (v > best) { best = v; bi = k; }
        }
        sh_cid[tid] = bi;
        g_cid[tid] = bi;
        g_lmda[tid] = lmda[tid];
    }
    __syncthreads();

    if (tid < K_CL) {
        int c = 0;
#pragma unroll
        for (int b = 0; b < B_DIM; ++b) c += (sh_cid[b] == tid);
        sh_cnt[tid] = c;
        g_count[tid] = c;
        g_curA[tid] = 0;
        g_curC[tid] = 0;
        g_doneA[tid] = 0;
        g_flag[tid] = (c == 0) ? 1 : 0;
    }
    __syncthreads();

    if (tid == 0) {
        int acc = 0;
#pragma unroll
        for (int k = 0; k < K_CL; ++k) {
            sh_off[k] = acc;
            g_pbase[k] = acc * C_DIM;
            acc += sh_cnt[k];
        }
    }
    __syncthreads();

    if (tid < K_CL) {
        int pos = sh_off[tid];
#pragma unroll
        for (int b = 0; b < B_DIM; ++b)
            if (sh_cid[b] == tid) sh_sorted_b[pos++] = b;
    }
    __syncthreads();

    for (int i = tid; i < BC; i += 256) {
        int b = sh_sorted_b[i >> 6];
        g_plane_order[i] = b * C_DIM + (i & 63);
    }
}

// ---------------------------------------------------------------------------
// Kernel B: phased persistent kernel.
// ---------------------------------------------------------------------------
__global__ __launch_bounds__(NTHR, 8) void k_main(const float* __restrict__ x,
                                                  float* __restrict__ out) {
    __shared__ float r1[8], r2[8];
    __shared__ int sh_t, sh_fin;

    const int tid = threadIdx.x;
    const int lane = tid & 31;
    const int wid = tid >> 5;

    for (int k = 0; k < K_CL; ++k) {
        const int cnt = g_count[k];
        const int ntq = cnt * C_DIM * 4;   // quarter tasks in this cluster
        const int pbase = g_pbase[k];
        if (ntq == 0) continue;

        // ---------------- Phase A: reduce (dynamic cursor) ----------------
        for (;;) {
            if (tid == 0) sh_t = atomicAdd(&g_curA[k], 1);
            __syncthreads();
            const int t = sh_t;
            __syncthreads();
            if (t >= ntq) break;

            const int plane = g_plane_order[pbase + (t >> 2)];
            const int q = t & 3;
            const float4* __restrict__ px =
                reinterpret_cast<const float4*>(x + (size_t)plane * HW + q * QF);
            float s1 = 0.f, s2 = 0.f;
#pragma unroll
            for (int i = tid; i < QF4; i += NTHR) {
                float4 v = px[i];   // evict-normal: stays in L2 for phase C
                s1 += (v.x + v.y) + (v.z + v.w);
                s2 += (v.x * v.x + v.y * v.y) + (v.z * v.z + v.w * v.w);
            }
#pragma unroll
            for (int off = 16; off > 0; off >>= 1) {
                s1 += __shfl_down_sync(0xffffffffu, s1, off);
                s2 += __shfl_down_sync(0xffffffffu, s2, off);
            }
            if (lane == 0) { r1[wid] = s1; r2[wid] = s2; }
            __syncthreads();
            if (tid == 0) {
                float t1 = ((r1[0] + r1[1]) + (r1[2] + r1[3])) +
                           ((r1[4] + r1[5]) + (r1[6] + r1[7]));
                float t2 = ((r2[0] + r2[1]) + (r2[2] + r2[3])) +
                           ((r2[4] + r2[5]) + (r2[6] + r2[7]));
                g_q1[plane * 4 + q] = t1;
                g_q2[plane * 4 + q] = t2;
                __threadfence();   // publish partials before done-count
                sh_fin = (atomicAdd(&g_doneA[k], 1) == ntq - 1);
            }
            __syncthreads();

            if (sh_fin) {
                // ---- finisher block: cluster stats + fused affine ----
                __threadfence();   // acquire: all partials visible
                if (tid < C_DIM) {
                    const int c = tid;
                    float cs1 = 0.f, cs2 = 0.f;
#pragma unroll
                    for (int b = 0; b < B_DIM; ++b) {
                        if (g_cid[b] == k) {
                            int base = (b * C_DIM + c) * 4;
                            cs1 += (__ldcg(&g_q1[base]) + __ldcg(&g_q1[base + 1])) +
                                   (__ldcg(&g_q1[base + 2]) + __ldcg(&g_q1[base + 3]));
                            cs2 += (__ldcg(&g_q2[base]) + __ldcg(&g_q2[base + 1])) +
                                   (__ldcg(&g_q2[base + 2]) + __ldcg(&g_q2[base + 3]));
                        }
                    }
                    float n_k = fmaxf((float)cnt * (float)HW, 1.0f);
                    float cmu = cs1 / n_k;
                    float cvar = (cs2 - n_k * cmu * cmu) / fmaxf(n_k - 1.0f, 1.0f);
                    float cstd = sqrtf(cvar + EPS);

                    const float inv_n = 1.0f / (float)HW;
                    const float inv_nm1 = 1.0f / (float)(HW - 1);
#pragma unroll
                    for (int b = 0; b < B_DIM; ++b) {
                        if (g_cid[b] == k) {
                            int bc = b * C_DIM + c;
                            int base = bc * 4;
                            float s1v = (__ldcg(&g_q1[base]) + __ldcg(&g_q1[base + 1])) +
                                        (__ldcg(&g_q1[base + 2]) + __ldcg(&g_q1[base + 3]));
                            float s2v = (__ldcg(&g_q2[base]) + __ldcg(&g_q2[base + 1])) +
                                        (__ldcg(&g_q2[base + 2]) + __ldcg(&g_q2[base + 3]));
                            float smu = s1v * inv_n;
                            float svar = (s2v - (float)HW * smu * smu) * inv_nm1;
                            float sstd = sqrtf(svar + EPS);
                            float l = g_lmda[b];
                            float std_mix = sstd * l + cstd * (1.0f - l);
                            float mu_mix = smu * l + cmu * (1.0f - l);
                            float scale = std_mix / sstd;
                            g_scale[bc] = scale;
                            g_bias[bc] = mu_mix - smu * scale;
                        }
                    }
                    __threadfence();   // each writer fences its own writes
                }
                __syncthreads();       // all writers fenced before flag
                if (tid == 0) g_flag[k] = 1;
            }
            __syncthreads();
        }

        // ------------- wait for cluster stats (wave-safe spin) -------------
        if (tid == 0) {
            while (!g_flag[k]) __nanosleep(64);
        }
        __syncthreads();

        // ---------------- Phase C: apply (L2-hot reads) ----------------
        for (;;) {
            if (tid == 0) sh_t = atomicAdd(&g_curC[k], 1);
            __syncthreads();
            const int t = sh_t;
            __syncthreads();
            if (t >= ntq) break;

            const int plane = g_plane_order[pbase + (t >> 2)];
            const int q = t & 3;
            const float scale = __ldcg(&g_scale[plane]);
            const float bias = __ldcg(&g_bias[plane]);
            const float4* __restrict__ px =
                reinterpret_cast<const float4*>(x + (size_t)plane * HW + q * QF);
            float4* __restrict__ po =
                reinterpret_cast<float4*>(out + (size_t)plane * HW + q * QF);
#pragma unroll
            for (int i = tid; i < QF4; i += NTHR) {
                float4 v = __ldcs(&px[i]);   // L2-hot; dead after this read
                v.x = fmaf(v.x, scale, bias);
                v.y = fmaf(v.y, scale, bias);
                v.z = fmaf(v.z, scale, bias);
                v.w = fmaf(v.w, scale, bias);
                __stcs(&po[i], v);           // streaming store
            }
        }
        // no barrier: phase C stragglers overlap next cluster's phase A
    }
}

extern "C" void kernel_launch(void* const* d_in, const int* in_sizes, int n_in,
                              void* d_out, int out_size) {
    const float* x = (const float*)d_in[0];            // [64,64,112,112]
    const float* cluster_map = (const float*)d_in[1];  // [1,64,8]
    const float* lmda = (const float*)d_in[2];         // [64,1,1,1]
    float* out = (float*)d_out;

    int dev = 0, sms = 148;
    cudaGetDevice(&dev);
    cudaDeviceGetAttribute(&sms, cudaDevAttrMultiProcessorCount, dev);
    if (sms < 1) sms = 148;
    int occ = 8;
    cudaOccupancyMaxActiveBlocksPerMultiprocessor(&occ, k_main, NTHR, 0);
    if (occ < 1) occ = 1;
    if (occ > 8) occ = 8;
    const int nb = occ * sms;   // full single wave (extra waves are harmless)

    k_schedule<<<1, 256>>>(cluster_map, lmda);
    k_main<<<nb, NTHR>>>(x, out);
}

// round 10
// speedup vs baseline: 1.7837x; 1.7837x over previous
#include <cuda_runtime.h>
#include <math.h>

#define B_DIM 64
#define C_DIM 64
#define K_CL 8
#define HW 12544            // floats per plane
#define QF 3136             // floats per quarter-plane
#define QF4 784             // float4 per quarter
#define BC (B_DIM * C_DIM)  // 4096 planes
#define EPS 1e-6f
#define NTHR 256

// ---- device scratch -------------------------------------------------------
__device__ int   g_cid[B_DIM];
__device__ float g_lmda[B_DIM];
__device__ int   g_count[K_CL];
__device__ int   g_pbase[K_CL];        // plane-order base of cluster
__device__ int   g_plane_order[BC];    // planes sorted cluster-major
__device__ float g_q1[BC * 4];         // per-quarter partial sums
__device__ float g_q2[BC * 4];
__device__ float g_cmu[K_CL * C_DIM];  // cluster stats (per channel)
__device__ float g_cstd[K_CL * C_DIM];
__device__ int   g_curA[K_CL];
__device__ int   g_curC[K_CL];
__device__ int   g_doneA[K_CL];
__device__ int   g_flag[K_CL];

// ---------------------------------------------------------------------------
// Kernel A: schedule (parallel, 1 block).
// ---------------------------------------------------------------------------
__global__ __launch_bounds__(256) void k_schedule(const float* __restrict__ cluster_map,
                                                  const float* __restrict__ lmda) {
    __shared__ int sh_cid[B_DIM];
    __shared__ int sh_sorted_b[B_DIM];
    __shared__ int sh_off[K_CL];
    __shared__ int sh_cnt[K_CL];

    const int tid = threadIdx.x;

    if (tid < B_DIM) {
        const float* row = cluster_map + tid * K_CL;
        float best = row[0];
        int bi = 0;
#pragma unroll
        for (int k = 1; k < K_CL; ++k) {
            float v = row[k];
            if (v > best) { best = v; bi = k; }
        }
        sh_cid[tid] = bi;
        g_cid[tid] = bi;
        g_lmda[tid] = lmda[tid];
    }
    __syncthreads();

    if (tid < K_CL) {
        int c = 0;
#pragma unroll
        for (int b = 0; b < B_DIM; ++b) c += (sh_cid[b] == tid);
        sh_cnt[tid] = c;
        g_count[tid] = c;
        g_curA[tid] = 0;
        g_curC[tid] = 0;
        g_doneA[tid] = 0;
        g_flag[tid] = (c == 0) ? 1 : 0;
    }
    __syncthreads();

    if (tid == 0) {
        int acc = 0;
#pragma unroll
        for (int k = 0; k < K_CL; ++k) {
            sh_off[k] = acc;
            g_pbase[k] = acc * C_DIM;
            acc += sh_cnt[k];
        }
    }
    __syncthreads();

    if (tid < K_CL) {
        int pos = sh_off[tid];
#pragma unroll
        for (int b = 0; b < B_DIM; ++b)
            if (sh_cid[b] == tid) sh_sorted_b[pos++] = b;
    }
    __syncthreads();

    for (int i = tid; i < BC; i += 256) {
        int b = sh_sorted_b[i >> 6];
        g_plane_order[i] = b * C_DIM + (i & 63);
    }
}

// ---------------------------------------------------------------------------
// Kernel B: pipelined persistent kernel. Segment k: A(k) interleaved with
// C(k-1). flag[k] rises during segment k, one full segment before C(k).
// ---------------------------------------------------------------------------
__global__ __launch_bounds__(NTHR, 8) void k_main(const float* __restrict__ x,
                                                  float* __restrict__ out) {
    __shared__ float r1[8], r2[8];
    __shared__ float scs1[NTHR], scs2[NTHR];
    __shared__ int sh_ta, sh_tc, sh_fin;

    const int tid = threadIdx.x;
    const int lane = tid & 31;
    const int wid = tid >> 5;

    for (int k = 0; k <= K_CL; ++k) {
        const int kc = k - 1;                                 // cluster to apply
        const int cntA = (k < K_CL) ? g_count[k] : 0;
        const int ntqA = cntA * C_DIM * 4;
        const int ntqC = (kc >= 0) ? g_count[kc] * C_DIM * 4 : 0;
        const int pbA = (k < K_CL) ? g_pbase[k] : 0;
        const int pbC = (kc >= 0) ? g_pbase[kc] : 0;
        bool hA = ntqA > 0, hC = ntqC > 0;   // used by tid 0 only
        bool flag_seen = false;

        for (;;) {
            if (tid == 0) {
                int ta = -1, tc = -1;
                if (hA) { ta = atomicAdd(&g_curA[k], 1);  if (ta >= ntqA) { ta = -1; hA = false; } }
                if (hC) { tc = atomicAdd(&g_curC[kc], 1); if (tc >= ntqC) { tc = -1; hC = false; } }
                sh_ta = ta;
                sh_tc = tc;
            }
            __syncthreads();
            const int ta = sh_ta;
            const int tc = sh_tc;
            if (ta < 0 && tc < 0) break;

            // ======================= A: reduce one quarter =======================
            if (ta >= 0) {
                const int plane = g_plane_order[pbA + (ta >> 2)];
                const int q = ta & 3;
                const float4* __restrict__ px =
                    reinterpret_cast<const float4*>(x + (size_t)plane * HW + q * QF);
                float s1 = 0.f, s2 = 0.f;
#pragma unroll
                for (int i = tid; i < QF4; i += NTHR) {
                    float4 v = px[i];   // evict-normal: stays in L2 for C(k)
                    s1 += (v.x + v.y) + (v.z + v.w);
                    s2 += (v.x * v.x + v.y * v.y) + (v.z * v.z + v.w * v.w);
                }
#pragma unroll
                for (int off = 16; off > 0; off >>= 1) {
                    s1 += __shfl_down_sync(0xffffffffu, s1, off);
                    s2 += __shfl_down_sync(0xffffffffu, s2, off);
                }
                if (lane == 0) { r1[wid] = s1; r2[wid] = s2; }
                __syncthreads();
                if (tid == 0) {
                    float t1 = ((r1[0] + r1[1]) + (r1[2] + r1[3])) +
                               ((r1[4] + r1[5]) + (r1[6] + r1[7]));
                    float t2 = ((r2[0] + r2[1]) + (r2[2] + r2[3])) +
                               ((r2[4] + r2[5]) + (r2[6] + r2[7]));
                    g_q1[plane * 4 + q] = t1;
                    g_q2[plane * 4 + q] = t2;
                    __threadfence();   // publish partials before done-count
                    sh_fin = (atomicAdd(&g_doneA[k], 1) == ntqA - 1);
                }
                __syncthreads();

                if (sh_fin) {
                    // ---- finisher: cluster stats, 256-thread parallel ----
                    __threadfence();   // acquire: all partials visible
                    const int c = tid & 63;
                    const int grp = tid >> 6;      // 0..3, 16 samples each
                    float cs1 = 0.f, cs2 = 0.f;
#pragma unroll
                    for (int bb = 0; bb < 16; ++bb) {
                        int b = grp * 16 + bb;
                        if (g_cid[b] == k) {
                            int base = (b * C_DIM + c) * 4;
                            cs1 += (__ldcg(&g_q1[base]) + __ldcg(&g_q1[base + 1])) +
                                   (__ldcg(&g_q1[base + 2]) + __ldcg(&g_q1[base + 3]));
                            cs2 += (__ldcg(&g_q2[base]) + __ldcg(&g_q2[base + 1])) +
                                   (__ldcg(&g_q2[base + 2]) + __ldcg(&g_q2[base + 3]));
                        }
                    }
                    scs1[tid] = cs1;
                    scs2[tid] = cs2;
                    __syncthreads();
                    if (tid < C_DIM) {
                        float t1 = (scs1[tid] + scs1[tid + 64]) +
                                   (scs1[tid + 128] + scs1[tid + 192]);
                        float t2 = (scs2[tid] + scs2[tid + 64]) +
                                   (scs2[tid + 128] + scs2[tid + 192]);
                        float n_k = fmaxf((float)cntA * (float)HW, 1.0f);
                        float cmu = t1 / n_k;
                        float cvar = (t2 - n_k * cmu * cmu) / fmaxf(n_k - 1.0f, 1.0f);
                        g_cmu[k * C_DIM + tid] = cmu;
                        g_cstd[k * C_DIM + tid] = sqrtf(cvar + EPS);
                        __threadfence();   // publish cluster stats
                    }
                    __syncthreads();
                    if (tid == 0) atomicExch(&g_flag[k], 1);
                }
                __syncthreads();
            }

            // ======================= C: apply one quarter =======================
            if (tc >= 0) {
                if (!flag_seen) {
                    if (tid == 0) {
                        while (!(*(volatile int*)&g_flag[kc])) __nanosleep(64);
                    }
                    __syncthreads();
                    flag_seen = true;
                }
                const int plane = g_plane_order[pbC + (tc >> 2)];
                const int q = tc & 3;
                const int b = plane >> 6;
                const int c = plane & 63;
                // per-plane affine from quarter sums + cluster stats (uniform)
                const int base = plane * 4;
                float s1 = (__ldcg(&g_q1[base]) + __ldcg(&g_q1[base + 1])) +
                           (__ldcg(&g_q1[base + 2]) + __ldcg(&g_q1[base + 3]));
                float s2 = (__ldcg(&g_q2[base]) + __ldcg(&g_q2[base + 1])) +
                           (__ldcg(&g_q2[base + 2]) + __ldcg(&g_q2[base + 3]));
                float smu = s1 * (1.0f / (float)HW);
                float svar = (s2 - (float)HW * smu * smu) * (1.0f / (float)(HW - 1));
                float sstd = sqrtf(svar + EPS);
                float cmu = __ldcg(&g_cmu[kc * C_DIM + c]);
                float cstd = __ldcg(&g_cstd[kc * C_DIM + c]);
                float l = g_lmda[b];
                float std_mix = sstd * l + cstd * (1.0f - l);
                float mu_mix = smu * l + cmu * (1.0f - l);
                float scale = std_mix / sstd;
                float bias = mu_mix - smu * scale;

                const float4* __restrict__ px =
                    reinterpret_cast<const float4*>(x + (size_t)plane * HW + q * QF);
                float4* __restrict__ po =
                    reinterpret_cast<float4*>(out + (size_t)plane * HW + q * QF);
#pragma unroll
                for (int i = tid; i < QF4; i += NTHR) {
                    float4 v = __ldcs(&px[i]);   // L2-hot; dead after this read
                    v.x = fmaf(v.x, scale, bias);
                    v.y = fmaf(v.y, scale, bias);
                    v.z = fmaf(v.z, scale, bias);
                    v.w = fmaf(v.w, scale, bias);
                    __stcs(&po[i], v);           // streaming store
                }
            }
            __syncthreads();   // protect sh_ta/sh_tc before next dequeue
        }
    }
}

extern "C" void kernel_launch(void* const* d_in, const int* in_sizes, int n_in,
                              void* d_out, int out_size) {
    const float* x = (const float*)d_in[0];            // [64,64,112,112]
    const float* cluster_map = (const float*)d_in[1];  // [1,64,8]
    const float* lmda = (const float*)d_in[2];         // [64,1,1,1]
    float* out = (float*)d_out;

    int dev = 0, sms = 148;
    cudaGetDevice(&dev);
    cudaDeviceGetAttribute(&sms, cudaDevAttrMultiProcessorCount, dev);
    if (sms < 1) sms = 148;
    int occ = 8;
    cudaOccupancyMaxActiveBlocksPerMultiprocessor(&occ, k_main, NTHR, 0);
    if (occ < 1) occ = 1;
    if (occ > 8) occ = 8;
    const int nb = occ * sms;   // exactly one resident wave

    k_schedule<<<1, 256>>>(cluster_map, lmda);
    k_main<<<nb, NTHR>>>(x, out);
}